// round 5
// baseline (speedup 1.0000x reference)
#include <cuda_runtime.h>
#include <cuda_bf16.h>
#include <cstdint>

#define N_NODES 100000
#define N_EDGES 1600000
#define D 128
#define CAP 64
#define OVF_CAP 8192

// ---------------- scratch (static device globals; no runtime allocation) ----
__device__ float g_support[(size_t)N_NODES * D];       // x @ W   (51.2 MB)
__device__ int   g_deg[N_NODES];
__device__ int2  g_bpack[(size_t)N_NODES * CAP];       // (src, val bits) packed
__device__ int   g_ovfn;
__device__ int   g_ovf_src[OVF_CAP];
__device__ int   g_ovf_dst[OVF_CAP];
__device__ float g_ovf_val[OVF_CAP];

__device__ __forceinline__ uint32_t cvt_tf32(float f) {
    uint32_t r;
    asm("cvt.rna.tf32.f32 %0, %1;" : "=r"(r) : "f"(f));
    return r;
}

// mma.sync m16n8k8 tf32: D += A*B (A row-major 16x8, B col-major 8x8)
#define MMA_TF32(d0, d1, d2, d3, a0, a1, a2, a3, b0, b1)                        \
    asm volatile(                                                               \
        "mma.sync.aligned.m16n8k8.row.col.f32.tf32.tf32.f32 "                   \
        "{%0,%1,%2,%3}, {%4,%5,%6,%7}, {%8,%9}, {%0,%1,%2,%3};"                 \
        : "+f"(d0), "+f"(d1), "+f"(d2), "+f"(d3)                                \
        : "r"(a0), "r"(a1), "r"(a2), "r"(a3), "r"(b0), "r"(b1))

// ---------------- 1) zero counters ------------------------------------------
__global__ void zero_kernel() {
    int i = blockIdx.x * blockDim.x + threadIdx.x;
    if (i < N_NODES) g_deg[i] = 0;
    if (i == 0) g_ovfn = 0;
}

// ---------------- 2) bucket edges by destination (packed 8B stores) ---------
__global__ void bucket_kernel(const int* __restrict__ esrc,
                              const int* __restrict__ edst,
                              const float* __restrict__ aval) {
    int e = blockIdx.x * blockDim.x + threadIdx.x;
    if (e >= N_EDGES) return;
    int d = edst[e];
    int s = esrc[e];
    float v = aval[e];
    int p = atomicAdd(&g_deg[d], 1);
    if (p < CAP) {
        g_bpack[d * CAP + p] = make_int2(s, __float_as_int(v));
    } else {
        int o = atomicAdd(&g_ovfn, 1);
        if (o < OVF_CAP) {
            g_ovf_src[o] = s;
            g_ovf_dst[o] = d;
            g_ovf_val[o] = v;
        }
    }
}

// ---------------- 3) support = x @ W  via mma.sync tf32 ---------------------
// Block: 256 threads = 8 warps (2x4 grid). M-tile 128 rows, N = 128.
// Warp tile: 64 rows x 32 cols -> 4 m-frags x 4 n-frags of m16n8k8, 16 k-steps.
// A staged in smem (stride 132 -> conflict-free); B (=W, 64KB) read directly
// from global via __ldg: it stays L1-resident, so no smem copy per block.
#define A_STRIDE 132
#define M_TILE 128
#define SM_GEMM (M_TILE * A_STRIDE * 4)               // 67584
#define GEMM_BLOCKS ((N_NODES + M_TILE - 1) / M_TILE) // 782

__global__ __launch_bounds__(256, 2)
void gemm_mma_kernel(const float* __restrict__ x,
                     const float* __restrict__ w,
                     float* __restrict__ support) {
    extern __shared__ uint32_t As[];         // [128][A_STRIDE]

    int tid  = threadIdx.x;
    int wid  = tid >> 5;
    int lane = tid & 31;
    int wr   = wid >> 2;        // warp row 0..1 -> rows wr*64
    int wc   = wid & 3;         // warp col 0..3 -> cols wc*32
    int lr   = lane >> 2;       // 0..7
    int lc   = lane & 3;        // 0..3
    int row0 = blockIdx.x * M_TILE;

    // stage A (x tile), tf32-converted, padded stride
    #pragma unroll
    for (int i = 0; i < 16; i++) {
        int idx = tid + i * 256;
        int r = idx >> 5, c4 = idx & 31;
        int gr = row0 + r;
        if (gr >= N_NODES) gr = N_NODES - 1;
        float4 v = ((const float4*)(x + (size_t)gr * 128))[c4];
        uint4 t;
        t.x = cvt_tf32(v.x); t.y = cvt_tf32(v.y);
        t.z = cvt_tf32(v.z); t.w = cvt_tf32(v.w);
        *(uint4*)&As[r * A_STRIDE + c4 * 4] = t;
    }
    __syncthreads();

    float acc[4][4][4];   // [m-frag][n-frag][c0..c3]
    #pragma unroll
    for (int m = 0; m < 4; m++)
        #pragma unroll
        for (int n = 0; n < 4; n++)
            #pragma unroll
            for (int q = 0; q < 4; q++) acc[m][n][q] = 0.f;

    #pragma unroll 4
    for (int ks = 0; ks < 16; ks++) {
        int k0 = ks * 8;
        uint32_t af[4][4], bf[4][2];
        #pragma unroll
        for (int n = 0; n < 4; n++) {
            int nn = wc * 32 + n * 8 + lr;
            bf[n][0] = cvt_tf32(__ldg(w + (k0 + lc) * 128 + nn));
            bf[n][1] = cvt_tf32(__ldg(w + (k0 + lc + 4) * 128 + nn));
        }
        #pragma unroll
        for (int m = 0; m < 4; m++) {
            int r = wr * 64 + m * 16 + lr;
            af[m][0] = As[r * A_STRIDE + k0 + lc];
            af[m][1] = As[(r + 8) * A_STRIDE + k0 + lc];
            af[m][2] = As[r * A_STRIDE + k0 + lc + 4];
            af[m][3] = As[(r + 8) * A_STRIDE + k0 + lc + 4];
        }
        #pragma unroll
        for (int m = 0; m < 4; m++)
            #pragma unroll
            for (int n = 0; n < 4; n++)
                MMA_TF32(acc[m][n][0], acc[m][n][1], acc[m][n][2], acc[m][n][3],
                         af[m][0], af[m][1], af[m][2], af[m][3],
                         bf[n][0], bf[n][1]);
    }

    // epilogue: c0,c1 at (row, 2*lc), c2,c3 at (row+8, 2*lc)
    #pragma unroll
    for (int m = 0; m < 4; m++) {
        int r = row0 + wr * 64 + m * 16 + lr;
        #pragma unroll
        for (int n = 0; n < 4; n++) {
            int col = wc * 32 + n * 8 + lc * 2;
            if (r < N_NODES) {
                float2 v0 = make_float2(acc[m][n][0], acc[m][n][1]);
                *(float2*)(support + (size_t)r * 128 + col) = v0;
            }
            if (r + 8 < N_NODES) {
                float2 v1 = make_float2(acc[m][n][2], acc[m][n][3]);
                *(float2*)(support + (size_t)(r + 8) * 128 + col) = v1;
            }
        }
    }
}

// ---------------- 4) gather + bias + residual + relu ------------------------
// One warp per destination node. Lane l owns one float4 (cols 4l..4l+3).
// Edge metadata packed (src,val) int2; read as int4 (2 edges per load).
// Next 4-edge batch prefetched into registers while current gathers fly.
__global__ __launch_bounds__(256)
void gather_kernel(const float* __restrict__ y,
                   const float* __restrict__ bias,
                   float* __restrict__ out) {
    int warp = (blockIdx.x * blockDim.x + threadIdx.x) >> 5;
    int lane = threadIdx.x & 31;
    if (warp >= N_NODES) return;
    int node = warp;

    const float4* sup4 = (const float4*)g_support;
    const int4* bp4 = (const int4*)&g_bpack[node * CAP];

    float4 acc = make_float4(0.f, 0.f, 0.f, 0.f);

    int dn = g_deg[node];
    int m  = dn < CAP ? dn : CAP;
    int nb = m >> 2;                 // full 4-edge batches

    int4 q0, q1;
    if (nb > 0) { q0 = bp4[0]; q1 = bp4[1]; }

    for (int b = 0; b < nb; b++) {
        int4 c0 = q0, c1 = q1;
        if (b + 1 < nb) { q0 = bp4[(b + 1) * 2]; q1 = bp4[(b + 1) * 2 + 1]; }
        float4 a0 = __ldcg(&sup4[(size_t)c0.x * 32 + lane]);
        float4 a1 = __ldcg(&sup4[(size_t)c0.z * 32 + lane]);
        float4 a2 = __ldcg(&sup4[(size_t)c1.x * 32 + lane]);
        float4 a3 = __ldcg(&sup4[(size_t)c1.z * 32 + lane]);
        float v0 = __int_as_float(c0.y), v1 = __int_as_float(c0.w);
        float v2 = __int_as_float(c1.y), v3 = __int_as_float(c1.w);
        acc.x = fmaf(v0, a0.x, acc.x); acc.y = fmaf(v0, a0.y, acc.y);
        acc.z = fmaf(v0, a0.z, acc.z); acc.w = fmaf(v0, a0.w, acc.w);
        acc.x = fmaf(v1, a1.x, acc.x); acc.y = fmaf(v1, a1.y, acc.y);
        acc.z = fmaf(v1, a1.z, acc.z); acc.w = fmaf(v1, a1.w, acc.w);
        acc.x = fmaf(v2, a2.x, acc.x); acc.y = fmaf(v2, a2.y, acc.y);
        acc.z = fmaf(v2, a2.z, acc.z); acc.w = fmaf(v2, a2.w, acc.w);
        acc.x = fmaf(v3, a3.x, acc.x); acc.y = fmaf(v3, a3.y, acc.y);
        acc.z = fmaf(v3, a3.z, acc.z); acc.w = fmaf(v3, a3.w, acc.w);
    }
    for (int j = nb * 4; j < m; j++) {
        int2 e = g_bpack[node * CAP + j];
        float v = __int_as_float(e.y);
        float4 sp = __ldcg(&sup4[(size_t)e.x * 32 + lane]);
        acc.x = fmaf(v, sp.x, acc.x);
        acc.y = fmaf(v, sp.y, acc.y);
        acc.z = fmaf(v, sp.z, acc.z);
        acc.w = fmaf(v, sp.w, acc.w);
    }

    if (dn > CAP) {  // statistically never; correctness safety net
        int oc = g_ovfn;
        if (oc > OVF_CAP) oc = OVF_CAP;
        for (int k = 0; k < oc; k++) {
            if (g_ovf_dst[k] == node) {
                int s   = g_ovf_src[k];
                float v = g_ovf_val[k];
                float4 sp = sup4[(size_t)s * 32 + lane];
                acc.x = fmaf(v, sp.x, acc.x);
                acc.y = fmaf(v, sp.y, acc.y);
                acc.z = fmaf(v, sp.z, acc.z);
                acc.w = fmaf(v, sp.w, acc.w);
            }
        }
    }

    float4 b = ((const float4*)bias)[lane];
    float4 yv = ((const float4*)y)[(size_t)node * 32 + lane];
    acc.x = fmaxf(acc.x + b.x + yv.x, 0.f);
    acc.y = fmaxf(acc.y + b.y + yv.y, 0.f);
    acc.z = fmaxf(acc.z + b.z + yv.z, 0.f);
    acc.w = fmaxf(acc.w + b.w + yv.w, 0.f);
    ((float4*)out)[(size_t)node * 32 + lane] = acc;
}

// ---------------- launch -----------------------------------------------------
extern "C" void kernel_launch(void* const* d_in, const int* in_sizes, int n_in,
                              void* d_out, int out_size) {
    const float* x    = (const float*)d_in[0];
    const float* y    = (const float*)d_in[1];
    const int*   esrc = (const int*)d_in[2];
    const int*   edst = (const int*)d_in[3];
    const float* aval = (const float*)d_in[4];
    const float* w    = (const float*)d_in[5];
    const float* bias = (const float*)d_in[6];
    float* out = (float*)d_out;

    float* support;
    cudaGetSymbolAddress((void**)&support, g_support);

    cudaFuncSetAttribute(gemm_mma_kernel,
                         cudaFuncAttributeMaxDynamicSharedMemorySize, SM_GEMM);

    zero_kernel<<<(N_NODES + 255) / 256, 256>>>();
    bucket_kernel<<<(N_EDGES + 255) / 256, 256>>>(esrc, edst, aval);
    gemm_mma_kernel<<<GEMM_BLOCKS, 256, SM_GEMM>>>(x, w, support);
    gather_kernel<<<(N_NODES * 32 + 255) / 256, 256>>>(y, bias, out);
}

// round 6
// speedup vs baseline: 1.4561x; 1.4561x over previous
#include <cuda_runtime.h>
#include <cuda_bf16.h>
#include <cstdint>

#define N_NODES 100000
#define N_EDGES 1600000
#define D 128
#define CAP 64
#define OVF_CAP 8192

// ---------------- scratch (static device globals; no runtime allocation) ----
__device__ float g_support[(size_t)N_NODES * D];       // x @ W   (51.2 MB)
__device__ int   g_deg[N_NODES];
__device__ int2  g_bpack[(size_t)N_NODES * CAP];       // (src, val bits) packed
__device__ int   g_ovfn;
__device__ int   g_ovf_src[OVF_CAP];
__device__ int   g_ovf_dst[OVF_CAP];
__device__ float g_ovf_val[OVF_CAP];

__device__ __forceinline__ uint32_t cvt_tf32(float f) {
    uint32_t r;
    asm("cvt.rna.tf32.f32 %0, %1;" : "=r"(r) : "f"(f));
    return r;
}
__device__ __forceinline__ uint32_t smem_u32(const void* p) {
    uint32_t a;
    asm("{ .reg .u64 t; cvta.to.shared.u64 t, %1; cvt.u32.u64 %0, t; }"
        : "=r"(a) : "l"(p));
    return a;
}
#define CP_ASYNC16(saddr, gptr) \
    asm volatile("cp.async.cg.shared.global [%0], [%1], 16;" :: "r"(saddr), "l"(gptr))
#define CP_COMMIT()  asm volatile("cp.async.commit_group;")
#define CP_WAIT0()   asm volatile("cp.async.wait_group 0;")

// mma.sync m16n8k8 tf32: D += A*B (A row-major 16x8, B col-major 8x8)
#define MMA_TF32(d0, d1, d2, d3, a0, a1, a2, a3, b0, b1)                        \
    asm volatile(                                                               \
        "mma.sync.aligned.m16n8k8.row.col.f32.tf32.tf32.f32 "                   \
        "{%0,%1,%2,%3}, {%4,%5,%6,%7}, {%8,%9}, {%0,%1,%2,%3};"                 \
        : "+f"(d0), "+f"(d1), "+f"(d2), "+f"(d3)                                \
        : "r"(a0), "r"(a1), "r"(a2), "r"(a3), "r"(b0), "r"(b1))

// ---------------- 1) zero counters ------------------------------------------
__global__ void zero_kernel() {
    int i = blockIdx.x * blockDim.x + threadIdx.x;
    if (i < N_NODES) g_deg[i] = 0;
    if (i == 0) g_ovfn = 0;
}

// ---------------- 2) bucket edges by destination (packed 8B stores) ---------
__global__ void bucket_kernel(const int* __restrict__ esrc,
                              const int* __restrict__ edst,
                              const float* __restrict__ aval) {
    int e = blockIdx.x * blockDim.x + threadIdx.x;
    if (e >= N_EDGES) return;
    int d = edst[e];
    int s = esrc[e];
    float v = aval[e];
    int p = atomicAdd(&g_deg[d], 1);
    if (p < CAP) {
        g_bpack[d * CAP + p] = make_int2(s, __float_as_int(v));
    } else {
        int o = atomicAdd(&g_ovfn, 1);
        if (o < OVF_CAP) {
            g_ovf_src[o] = s;
            g_ovf_dst[o] = d;
            g_ovf_val[o] = v;
        }
    }
}

// ---------------- 3) support = x @ W  via mma.sync tf32 ---------------------
// Persistent 148 CTAs x 256 threads (8 warps, 2x4). Tile = 128 rows.
// A double-buffered in smem via cp.async (raw fp32; cvt at fragment load).
// B = W read via __ldg (64KB, L1-resident). Warp tile 64x32 (4x4 m16n8k8).
#define A_STRIDE 132
#define M_TILE 128
#define BUF_U32 (M_TILE * A_STRIDE)                   // 16896 u32 = 67584 B
#define SM_GEMM (2 * BUF_U32 * 4)                     // 135168
#define TILES ((N_NODES + M_TILE - 1) / M_TILE)       // 782
#define GEMM_CTAS 148

__device__ __forceinline__ void stage_async(uint32_t sbuf,
                                            const float* __restrict__ x,
                                            int tile, int tid) {
    int row0 = tile * M_TILE;
    #pragma unroll
    for (int i = 0; i < 16; i++) {
        int idx = tid + i * 256;
        int r = idx >> 5, c4 = idx & 31;
        int gr = row0 + r;
        if (gr >= N_NODES) gr = N_NODES - 1;
        uint32_t sa = sbuf + (uint32_t)(r * A_STRIDE + c4 * 4) * 4u;
        CP_ASYNC16(sa, x + (size_t)gr * 128 + c4 * 4);
    }
}

__global__ __launch_bounds__(256, 1)
void gemm_mma_kernel(const float* __restrict__ x,
                     const float* __restrict__ w,
                     float* __restrict__ support) {
    extern __shared__ uint32_t sm[];
    float* buf[2] = { (float*)sm, (float*)(sm + BUF_U32) };
    uint32_t sbase = smem_u32(sm);

    int tid  = threadIdx.x;
    int wid  = tid >> 5;
    int lane = tid & 31;
    int wr   = wid >> 2;        // warp row 0..1 -> rows wr*64
    int wc   = wid & 3;         // warp col 0..3 -> cols wc*32
    int lr   = lane >> 2;       // 0..7
    int lc   = lane & 3;        // 0..3

    int tile = blockIdx.x;
    if (tile >= TILES) return;

    int cur = 0;
    stage_async(sbase, x, tile, tid);
    CP_COMMIT();
    CP_WAIT0();
    __syncthreads();

    while (tile < TILES) {
        int next = tile + GEMM_CTAS;
        if (next < TILES) {
            stage_async(sbase + (cur ^ 1) * (BUF_U32 * 4), x, next, tid);
            CP_COMMIT();
        }

        const float* As = buf[cur];
        float acc[4][4][4];
        #pragma unroll
        for (int m = 0; m < 4; m++)
            #pragma unroll
            for (int n = 0; n < 4; n++)
                #pragma unroll
                for (int q = 0; q < 4; q++) acc[m][n][q] = 0.f;

        #pragma unroll 4
        for (int ks = 0; ks < 16; ks++) {
            int k0 = ks * 8;
            uint32_t af[4][4], bf[4][2];
            #pragma unroll
            for (int n = 0; n < 4; n++) {
                int nn = wc * 32 + n * 8 + lr;
                bf[n][0] = cvt_tf32(__ldg(w + (k0 + lc) * 128 + nn));
                bf[n][1] = cvt_tf32(__ldg(w + (k0 + lc + 4) * 128 + nn));
            }
            #pragma unroll
            for (int m = 0; m < 4; m++) {
                int r = wr * 64 + m * 16 + lr;
                af[m][0] = cvt_tf32(As[r * A_STRIDE + k0 + lc]);
                af[m][1] = cvt_tf32(As[(r + 8) * A_STRIDE + k0 + lc]);
                af[m][2] = cvt_tf32(As[r * A_STRIDE + k0 + lc + 4]);
                af[m][3] = cvt_tf32(As[(r + 8) * A_STRIDE + k0 + lc + 4]);
            }
            #pragma unroll
            for (int m = 0; m < 4; m++)
                #pragma unroll
                for (int n = 0; n < 4; n++)
                    MMA_TF32(acc[m][n][0], acc[m][n][1], acc[m][n][2], acc[m][n][3],
                             af[m][0], af[m][1], af[m][2], af[m][3],
                             bf[n][0], bf[n][1]);
        }

        // epilogue: c0,c1 at (row, 2*lc), c2,c3 at (row+8, 2*lc)
        int row0 = tile * M_TILE;
        #pragma unroll
        for (int m = 0; m < 4; m++) {
            int r = row0 + wr * 64 + m * 16 + lr;
            #pragma unroll
            for (int n = 0; n < 4; n++) {
                int col = wc * 32 + n * 8 + lc * 2;
                if (r < N_NODES)
                    *(float2*)(support + (size_t)r * 128 + col) =
                        make_float2(acc[m][n][0], acc[m][n][1]);
                if (r + 8 < N_NODES)
                    *(float2*)(support + (size_t)(r + 8) * 128 + col) =
                        make_float2(acc[m][n][2], acc[m][n][3]);
            }
        }

        if (next < TILES) CP_WAIT0();
        __syncthreads();
        cur ^= 1;
        tile = next;
    }
}

// ---------------- 4) gather + bias + residual + relu ------------------------
// One warp per destination node. Lane l owns one float4 (cols 4l..4l+3).
// Simple loop (round-2 structure): default-cached loads so L1 captures the
// ~16x reuse of support rows; packed int2 edge metadata (one LDG.64).
__global__ __launch_bounds__(256)
void gather_kernel(const float* __restrict__ y,
                   const float* __restrict__ bias,
                   float* __restrict__ out) {
    int warp = (blockIdx.x * blockDim.x + threadIdx.x) >> 5;
    int lane = threadIdx.x & 31;
    if (warp >= N_NODES) return;
    int node = warp;

    const float4* sup4 = (const float4*)g_support;
    float4 b = ((const float4*)bias)[lane];
    float4 acc = ((const float4*)y)[(size_t)node * 32 + lane];
    acc.x += b.x; acc.y += b.y; acc.z += b.z; acc.w += b.w;

    int dn = g_deg[node];
    int m  = dn < CAP ? dn : CAP;
    int base = node * CAP;

    #pragma unroll 2
    for (int j = 0; j < m; j++) {
        int2 e = g_bpack[base + j];
        float v = __int_as_float(e.y);
        float4 sp = sup4[(size_t)e.x * 32 + lane];
        acc.x = fmaf(v, sp.x, acc.x);
        acc.y = fmaf(v, sp.y, acc.y);
        acc.z = fmaf(v, sp.z, acc.z);
        acc.w = fmaf(v, sp.w, acc.w);
    }

    if (dn > CAP) {  // statistically never; correctness safety net
        int oc = g_ovfn;
        if (oc > OVF_CAP) oc = OVF_CAP;
        for (int k = 0; k < oc; k++) {
            if (g_ovf_dst[k] == node) {
                int s   = g_ovf_src[k];
                float v = g_ovf_val[k];
                float4 sp = sup4[(size_t)s * 32 + lane];
                acc.x = fmaf(v, sp.x, acc.x);
                acc.y = fmaf(v, sp.y, acc.y);
                acc.z = fmaf(v, sp.z, acc.z);
                acc.w = fmaf(v, sp.w, acc.w);
            }
        }
    }

    acc.x = fmaxf(acc.x, 0.f);
    acc.y = fmaxf(acc.y, 0.f);
    acc.z = fmaxf(acc.z, 0.f);
    acc.w = fmaxf(acc.w, 0.f);
    ((float4*)out)[(size_t)node * 32 + lane] = acc;
}

// ---------------- launch -----------------------------------------------------
extern "C" void kernel_launch(void* const* d_in, const int* in_sizes, int n_in,
                              void* d_out, int out_size) {
    const float* x    = (const float*)d_in[0];
    const float* y    = (const float*)d_in[1];
    const int*   esrc = (const int*)d_in[2];
    const int*   edst = (const int*)d_in[3];
    const float* aval = (const float*)d_in[4];
    const float* w    = (const float*)d_in[5];
    const float* bias = (const float*)d_in[6];
    float* out = (float*)d_out;

    float* support;
    cudaGetSymbolAddress((void**)&support, g_support);

    cudaFuncSetAttribute(gemm_mma_kernel,
                         cudaFuncAttributeMaxDynamicSharedMemorySize, SM_GEMM);

    zero_kernel<<<(N_NODES + 255) / 256, 256>>>();
    bucket_kernel<<<(N_EDGES + 255) / 256, 256>>>(esrc, edst, aval);
    gemm_mma_kernel<<<GEMM_CTAS, 256, SM_GEMM>>>(x, w, support);
    gather_kernel<<<(N_NODES * 32 + 255) / 256, 256>>>(y, bias, out);
}

// round 8
// speedup vs baseline: 1.5897x; 1.0917x over previous
#include <cuda_runtime.h>
#include <cuda_bf16.h>
#include <cstdint>

#define N_NODES 100000
#define N_EDGES 1600000
#define D 128
#define CAP 64
#define OVF_CAP 8192

// ---------------- scratch (static device globals; no runtime allocation) ----
__device__ float g_support[(size_t)N_NODES * D];       // x @ W   (51.2 MB)
__device__ int   g_deg[N_NODES];
__device__ int2  g_bpack[(size_t)N_NODES * CAP];       // (src, val bits) packed
__device__ int   g_ovfn;
__device__ int   g_ovf_src[OVF_CAP];
__device__ int   g_ovf_dst[OVF_CAP];
__device__ float g_ovf_val[OVF_CAP];

__device__ __forceinline__ uint32_t cvt_tf32(float f) {
    uint32_t r;
    asm("cvt.rna.tf32.f32 %0, %1;" : "=r"(r) : "f"(f));
    return r;
}
__device__ __forceinline__ uint32_t smem_u32(const void* p) {
    uint32_t a;
    asm("{ .reg .u64 t; cvta.to.shared.u64 t, %1; cvt.u32.u64 %0, t; }"
        : "=r"(a) : "l"(p));
    return a;
}
#define CP_ASYNC16(saddr, gptr) \
    asm volatile("cp.async.cg.shared.global [%0], [%1], 16;" :: "r"(saddr), "l"(gptr))
#define CP_COMMIT()  asm volatile("cp.async.commit_group;")
#define CP_WAIT0()   asm volatile("cp.async.wait_group 0;")

// mma.sync m16n8k8 tf32: D += A*B (A row-major 16x8, B col-major 8x8)
#define MMA_TF32(d0, d1, d2, d3, a0, a1, a2, a3, b0, b1)                        \
    asm volatile(                                                               \
        "mma.sync.aligned.m16n8k8.row.col.f32.tf32.tf32.f32 "                   \
        "{%0,%1,%2,%3}, {%4,%5,%6,%7}, {%8,%9}, {%0,%1,%2,%3};"                 \
        : "+f"(d0), "+f"(d1), "+f"(d2), "+f"(d3)                                \
        : "r"(a0), "r"(a1), "r"(a2), "r"(a3), "r"(b0), "r"(b1))

// ---------------- 1) zero counters ------------------------------------------
__global__ void zero_kernel() {
    int i = blockIdx.x * blockDim.x + threadIdx.x;
    if (i < N_NODES) g_deg[i] = 0;
    if (i == 0) g_ovfn = 0;
}

// ---------------- 2) bucket edges by destination (packed 8B stores) ---------
__global__ void bucket_kernel(const int* __restrict__ esrc,
                              const int* __restrict__ edst,
                              const float* __restrict__ aval) {
    int e = blockIdx.x * blockDim.x + threadIdx.x;
    if (e >= N_EDGES) return;
    int d = edst[e];
    int s = esrc[e];
    float v = aval[e];
    int p = atomicAdd(&g_deg[d], 1);
    if (p < CAP) {
        g_bpack[d * CAP + p] = make_int2(s, __float_as_int(v));
    } else {
        int o = atomicAdd(&g_ovfn, 1);
        if (o < OVF_CAP) {
            g_ovf_src[o] = s;
            g_ovf_dst[o] = d;
            g_ovf_val[o] = v;
        }
    }
}

// ---------------- 3) support = x @ W  via mma.sync tf32 ---------------------
// Persistent 148 CTAs x 256 threads (8 warps, 2x4). Tile = 128 rows.
// A double-buffered via cp.async, fed RAW fp32 to the tf32 MMA (HW truncates).
// B = W converted to tf32 (RNA) into smem ONCE per CTA; inner loop = LDS+MMA.
#define A_STRIDE 132
#define B_STRIDE 136
#define M_TILE 128
#define BUF_U32 (M_TILE * A_STRIDE)                   // 16896 u32 = 67584 B
#define B_OFF   (2 * BUF_U32)                         // after both A buffers
#define SM_GEMM (2 * BUF_U32 * 4 + 128 * B_STRIDE * 4)  // 204800 B
#define TILES ((N_NODES + M_TILE - 1) / M_TILE)       // 782
#define GEMM_CTAS 148

__device__ __forceinline__ void stage_async(uint32_t sbuf,
                                            const float* __restrict__ x,
                                            int tile, int tid) {
    int row0 = tile * M_TILE;
    #pragma unroll
    for (int i = 0; i < 16; i++) {
        int idx = tid + i * 256;
        int r = idx >> 5, c4 = idx & 31;
        int gr = row0 + r;
        if (gr >= N_NODES) gr = N_NODES - 1;
        uint32_t sa = sbuf + (uint32_t)(r * A_STRIDE + c4 * 4) * 4u;
        CP_ASYNC16(sa, x + (size_t)gr * 128 + c4 * 4);
    }
}

__global__ __launch_bounds__(256, 1)
void gemm_mma_kernel(const float* __restrict__ x,
                     const float* __restrict__ w,
                     float* __restrict__ support) {
    extern __shared__ uint32_t sm[];
    uint32_t* bufA[2] = { sm, sm + BUF_U32 };
    uint32_t* Bs = sm + B_OFF;               // [128][B_STRIDE] tf32
    uint32_t sbase = smem_u32(sm);

    int tid  = threadIdx.x;
    int wid  = tid >> 5;
    int lane = tid & 31;
    int wr   = wid >> 2;        // warp row 0..1 -> rows wr*64
    int wc   = wid & 3;         // warp col 0..3 -> cols wc*32
    int lr   = lane >> 2;       // 0..7
    int lc   = lane & 3;        // 0..3

    int tile = blockIdx.x;
    if (tile >= TILES) return;

    // stage first A tile async, convert B to smem meanwhile
    int cur = 0;
    stage_async(sbase, x, tile, tid);
    CP_COMMIT();
    for (int idx = tid; idx < 128 * 32; idx += 256) {
        int k = idx >> 5, c4 = idx & 31;
        float4 v = ((const float4*)w)[k * 32 + c4];
        uint4 t;
        t.x = cvt_tf32(v.x); t.y = cvt_tf32(v.y);
        t.z = cvt_tf32(v.z); t.w = cvt_tf32(v.w);
        *(uint4*)&Bs[k * B_STRIDE + c4 * 4] = t;
    }
    CP_WAIT0();
    __syncthreads();

    while (tile < TILES) {
        int next = tile + GEMM_CTAS;
        if (next < TILES) {
            stage_async(sbase + (cur ^ 1) * (BUF_U32 * 4), x, next, tid);
            CP_COMMIT();
        }

        const uint32_t* As = bufA[cur];
        float acc[4][4][4];
        #pragma unroll
        for (int m = 0; m < 4; m++)
            #pragma unroll
            for (int n = 0; n < 4; n++)
                #pragma unroll
                for (int q = 0; q < 4; q++) acc[m][n][q] = 0.f;

        #pragma unroll 4
        for (int ks = 0; ks < 16; ks++) {
            int k0 = ks * 8;
            uint32_t af[4][4], bf[4][2];
            #pragma unroll
            for (int n = 0; n < 4; n++) {
                int nn = wc * 32 + n * 8 + lr;
                bf[n][0] = Bs[(k0 + lc) * B_STRIDE + nn];
                bf[n][1] = Bs[(k0 + lc + 4) * B_STRIDE + nn];
            }
            #pragma unroll
            for (int m = 0; m < 4; m++) {
                int r = wr * 64 + m * 16 + lr;
                af[m][0] = As[r * A_STRIDE + k0 + lc];
                af[m][1] = As[(r + 8) * A_STRIDE + k0 + lc];
                af[m][2] = As[r * A_STRIDE + k0 + lc + 4];
                af[m][3] = As[(r + 8) * A_STRIDE + k0 + lc + 4];
            }
            #pragma unroll
            for (int m = 0; m < 4; m++)
                #pragma unroll
                for (int n = 0; n < 4; n++)
                    MMA_TF32(acc[m][n][0], acc[m][n][1], acc[m][n][2], acc[m][n][3],
                             af[m][0], af[m][1], af[m][2], af[m][3],
                             bf[n][0], bf[n][1]);
        }

        // epilogue: c0,c1 at (row, 2*lc), c2,c3 at (row+8, 2*lc)
        int row0 = tile * M_TILE;
        #pragma unroll
        for (int m = 0; m < 4; m++) {
            int r = row0 + wr * 64 + m * 16 + lr;
            #pragma unroll
            for (int n = 0; n < 4; n++) {
                int col = wc * 32 + n * 8 + lc * 2;
                if (r < N_NODES)
                    *(float2*)(support + (size_t)r * 128 + col) =
                        make_float2(acc[m][n][0], acc[m][n][1]);
                if (r + 8 < N_NODES)
                    *(float2*)(support + (size_t)(r + 8) * 128 + col) =
                        make_float2(acc[m][n][2], acc[m][n][3]);
            }
        }

        if (next < TILES) CP_WAIT0();
        __syncthreads();
        cur ^= 1;
        tile = next;
    }
}

// ---------------- 4) gather + bias + residual + relu ------------------------
// One warp per destination node. Lane l owns one float4 (cols 4l..4l+3).
// Simple loop, default-cached loads so L1 captures support-row reuse.
__global__ __launch_bounds__(256)
void gather_kernel(const float* __restrict__ y,
                   const float* __restrict__ bias,
                   float* __restrict__ out) {
    int warp = (blockIdx.x * blockDim.x + threadIdx.x) >> 5;
    int lane = threadIdx.x & 31;
    if (warp >= N_NODES) return;
    int node = warp;

    const float4* sup4 = (const float4*)g_support;
    float4 b = ((const float4*)bias)[lane];
    float4 acc = ((const float4*)y)[(size_t)node * 32 + lane];
    acc.x += b.x; acc.y += b.y; acc.z += b.z; acc.w += b.w;

    int dn = g_deg[node];
    int m  = dn < CAP ? dn : CAP;
    int base = node * CAP;

    #pragma unroll 2
    for (int j = 0; j < m; j++) {
        int2 e = g_bpack[base + j];
        float v = __int_as_float(e.y);
        float4 sp = sup4[(size_t)e.x * 32 + lane];
        acc.x = fmaf(v, sp.x, acc.x);
        acc.y = fmaf(v, sp.y, acc.y);
        acc.z = fmaf(v, sp.z, acc.z);
        acc.w = fmaf(v, sp.w, acc.w);
    }

    if (dn > CAP) {  // statistically never; correctness safety net
        int oc = g_ovfn;
        if (oc > OVF_CAP) oc = OVF_CAP;
        for (int k = 0; k < oc; k++) {
            if (g_ovf_dst[k] == node) {
                int s   = g_ovf_src[k];
                float v = g_ovf_val[k];
                float4 sp = sup4[(size_t)s * 32 + lane];
                acc.x = fmaf(v, sp.x, acc.x);
                acc.y = fmaf(v, sp.y, acc.y);
                acc.z = fmaf(v, sp.z, acc.z);
                acc.w = fmaf(v, sp.w, acc.w);
            }
        }
    }

    acc.x = fmaxf(acc.x, 0.f);
    acc.y = fmaxf(acc.y, 0.f);
    acc.z = fmaxf(acc.z, 0.f);
    acc.w = fmaxf(acc.w, 0.f);
    ((float4*)out)[(size_t)node * 32 + lane] = acc;
}

// ---------------- launch -----------------------------------------------------
extern "C" void kernel_launch(void* const* d_in, const int* in_sizes, int n_in,
                              void* d_out, int out_size) {
    const float* x    = (const float*)d_in[0];
    const float* y    = (const float*)d_in[1];
    const int*   esrc = (const int*)d_in[2];
    const int*   edst = (const int*)d_in[3];
    const float* aval = (const float*)d_in[4];
    const float* w    = (const float*)d_in[5];
    const float* bias = (const float*)d_in[6];
    float* out = (float*)d_out;

    float* support;
    cudaGetSymbolAddress((void**)&support, g_support);

    cudaFuncSetAttribute(gemm_mma_kernel,
                         cudaFuncAttributeMaxDynamicSharedMemorySize, SM_GEMM);

    zero_kernel<<<(N_NODES + 255) / 256, 256>>>();
    bucket_kernel<<<(N_EDGES + 255) / 256, 256>>>(esrc, edst, aval);
    gemm_mma_kernel<<<GEMM_CTAS, 256, SM_GEMM>>>(x, w, support);
    gather_kernel<<<(N_NODES * 32 + 255) / 256, 256>>>(y, bias, out);
}

// round 10
// speedup vs baseline: 1.7327x; 1.0899x over previous
#include <cuda_runtime.h>
#include <cuda_bf16.h>
#include <cuda_fp16.h>
#include <cstdint>

#define N_NODES 100000
#define N_EDGES 1600000
#define D 128
#define CAP 64
#define OVF_CAP 8192

// ---------------- scratch (static device globals; no runtime allocation) ----
__device__ __half g_suph[(size_t)N_NODES * D];         // x @ W in fp16 (25.6 MB)
__device__ int    g_deg[N_NODES];
__device__ int2   g_bpack[(size_t)N_NODES * CAP];      // (src, val bits) packed
__device__ int    g_ovfn;
__device__ int    g_ovf_src[OVF_CAP];
__device__ int    g_ovf_dst[OVF_CAP];
__device__ float  g_ovf_val[OVF_CAP];

__device__ __forceinline__ uint32_t cvt_tf32(float f) {
    uint32_t r;
    asm("cvt.rna.tf32.f32 %0, %1;" : "=r"(r) : "f"(f));
    return r;
}
__device__ __forceinline__ uint32_t smem_u32(const void* p) {
    uint32_t a;
    asm("{ .reg .u64 t; cvta.to.shared.u64 t, %1; cvt.u32.u64 %0, t; }"
        : "=r"(a) : "l"(p));
    return a;
}
#define CP_ASYNC16(saddr, gptr) \
    asm volatile("cp.async.cg.shared.global [%0], [%1], 16;" :: "r"(saddr), "l"(gptr))
#define CP_COMMIT()  asm volatile("cp.async.commit_group;")
#define CP_WAIT0()   asm volatile("cp.async.wait_group 0;")

// mma.sync m16n8k8 tf32: D += A*B (A row-major 16x8, B col-major 8x8)
#define MMA_TF32(d0, d1, d2, d3, a0, a1, a2, a3, b0, b1)                        \
    asm volatile(                                                               \
        "mma.sync.aligned.m16n8k8.row.col.f32.tf32.tf32.f32 "                   \
        "{%0,%1,%2,%3}, {%4,%5,%6,%7}, {%8,%9}, {%0,%1,%2,%3};"                 \
        : "+f"(d0), "+f"(d1), "+f"(d2), "+f"(d3)                                \
        : "r"(a0), "r"(a1), "r"(a2), "r"(a3), "r"(b0), "r"(b1))

// ---------------- 1) zero counters ------------------------------------------
__global__ void zero_kernel() {
    int i = blockIdx.x * blockDim.x + threadIdx.x;
    if (i < N_NODES) g_deg[i] = 0;
    if (i == 0) g_ovfn = 0;
}

// ---------------- 2) bucket edges by destination (packed 8B stores) ---------
__global__ void bucket_kernel(const int* __restrict__ esrc,
                              const int* __restrict__ edst,
                              const float* __restrict__ aval) {
    int e = blockIdx.x * blockDim.x + threadIdx.x;
    if (e >= N_EDGES) return;
    int d = edst[e];
    int s = esrc[e];
    float v = aval[e];
    int p = atomicAdd(&g_deg[d], 1);
    if (p < CAP) {
        g_bpack[d * CAP + p] = make_int2(s, __float_as_int(v));
    } else {
        int o = atomicAdd(&g_ovfn, 1);
        if (o < OVF_CAP) {
            g_ovf_src[o] = s;
            g_ovf_dst[o] = d;
            g_ovf_val[o] = v;
        }
    }
}

// ---------------- 3) support = x @ W  via mma.sync tf32, fp16 output --------
// Persistent 148 CTAs x 256 threads (8 warps, 2x4). Tile = 128 rows.
// A double-buffered via cp.async, fed RAW fp32 to the tf32 MMA (HW truncates).
// B = W converted to tf32 (RNA) into smem ONCE per CTA; inner loop = LDS+MMA.
// Epilogue rounds to fp16 (RN) -> halves gather traffic downstream.
#define A_STRIDE 132
#define B_STRIDE 136
#define M_TILE 128
#define BUF_U32 (M_TILE * A_STRIDE)                   // 16896 u32 = 67584 B
#define B_OFF   (2 * BUF_U32)                         // after both A buffers
#define SM_GEMM (2 * BUF_U32 * 4 + 128 * B_STRIDE * 4)  // 204800 B
#define TILES ((N_NODES + M_TILE - 1) / M_TILE)       // 782
#define GEMM_CTAS 148

__device__ __forceinline__ void stage_async(uint32_t sbuf,
                                            const float* __restrict__ x,
                                            int tile, int tid) {
    int row0 = tile * M_TILE;
    #pragma unroll
    for (int i = 0; i < 16; i++) {
        int idx = tid + i * 256;
        int r = idx >> 5, c4 = idx & 31;
        int gr = row0 + r;
        if (gr >= N_NODES) gr = N_NODES - 1;
        uint32_t sa = sbuf + (uint32_t)(r * A_STRIDE + c4 * 4) * 4u;
        CP_ASYNC16(sa, x + (size_t)gr * 128 + c4 * 4);
    }
}

__global__ __launch_bounds__(256, 1)
void gemm_mma_kernel(const float* __restrict__ x,
                     const float* __restrict__ w,
                     __half* __restrict__ suph) {
    extern __shared__ uint32_t sm[];
    uint32_t* bufA[2] = { sm, sm + BUF_U32 };
    uint32_t* Bs = sm + B_OFF;               // [128][B_STRIDE] tf32
    uint32_t sbase = smem_u32(sm);

    int tid  = threadIdx.x;
    int wid  = tid >> 5;
    int lane = tid & 31;
    int wr   = wid >> 2;        // warp row 0..1 -> rows wr*64
    int wc   = wid & 3;         // warp col 0..3 -> cols wc*32
    int lr   = lane >> 2;       // 0..7
    int lc   = lane & 3;        // 0..3

    int tile = blockIdx.x;
    if (tile >= TILES) return;

    // stage first A tile async, convert B to smem meanwhile
    int cur = 0;
    stage_async(sbase, x, tile, tid);
    CP_COMMIT();
    for (int idx = tid; idx < 128 * 32; idx += 256) {
        int k = idx >> 5, c4 = idx & 31;
        float4 v = ((const float4*)w)[k * 32 + c4];
        uint4 t;
        t.x = cvt_tf32(v.x); t.y = cvt_tf32(v.y);
        t.z = cvt_tf32(v.z); t.w = cvt_tf32(v.w);
        *(uint4*)&Bs[k * B_STRIDE + c4 * 4] = t;
    }
    CP_WAIT0();
    __syncthreads();

    while (tile < TILES) {
        int next = tile + GEMM_CTAS;
        if (next < TILES) {
            stage_async(sbase + (cur ^ 1) * (BUF_U32 * 4), x, next, tid);
            CP_COMMIT();
        }

        const uint32_t* As = bufA[cur];
        float acc[4][4][4];
        #pragma unroll
        for (int m = 0; m < 4; m++)
            #pragma unroll
            for (int n = 0; n < 4; n++)
                #pragma unroll
                for (int q = 0; q < 4; q++) acc[m][n][q] = 0.f;

        #pragma unroll 4
        for (int ks = 0; ks < 16; ks++) {
            int k0 = ks * 8;
            uint32_t af[4][4], bf[4][2];
            #pragma unroll
            for (int n = 0; n < 4; n++) {
                int nn = wc * 32 + n * 8 + lr;
                bf[n][0] = Bs[(k0 + lc) * B_STRIDE + nn];
                bf[n][1] = Bs[(k0 + lc + 4) * B_STRIDE + nn];
            }
            #pragma unroll
            for (int m = 0; m < 4; m++) {
                int r = wr * 64 + m * 16 + lr;
                af[m][0] = As[r * A_STRIDE + k0 + lc];
                af[m][1] = As[(r + 8) * A_STRIDE + k0 + lc];
                af[m][2] = As[r * A_STRIDE + k0 + lc + 4];
                af[m][3] = As[(r + 8) * A_STRIDE + k0 + lc + 4];
            }
            #pragma unroll
            for (int m = 0; m < 4; m++)
                #pragma unroll
                for (int n = 0; n < 4; n++)
                    MMA_TF32(acc[m][n][0], acc[m][n][1], acc[m][n][2], acc[m][n][3],
                             af[m][0], af[m][1], af[m][2], af[m][3],
                             bf[n][0], bf[n][1]);
        }

        // epilogue: fp16 (RN). c0,c1 at (row, 2*lc), c2,c3 at (row+8, 2*lc)
        int row0 = tile * M_TILE;
        #pragma unroll
        for (int m = 0; m < 4; m++) {
            int r = row0 + wr * 64 + m * 16 + lr;
            #pragma unroll
            for (int n = 0; n < 4; n++) {
                int col = wc * 32 + n * 8 + lc * 2;
                if (r < N_NODES)
                    *(__half2*)(suph + (size_t)r * 128 + col) =
                        __floats2half2_rn(acc[m][n][0], acc[m][n][1]);
                if (r + 8 < N_NODES)
                    *(__half2*)(suph + (size_t)(r + 8) * 128 + col) =
                        __floats2half2_rn(acc[m][n][2], acc[m][n][3]);
            }
        }

        if (next < TILES) CP_WAIT0();
        __syncthreads();
        cur ^= 1;
        tile = next;
    }
}

// ---------------- 4) gather + bias + residual + relu ------------------------
// One warp per destination node. Lane l owns cols 4l..4l+3 (8B fp16 load).
__global__ __launch_bounds__(256)
void gather_kernel(const float* __restrict__ y,
                   const float* __restrict__ bias,
                   float* __restrict__ out) {
    int warp = (blockIdx.x * blockDim.x + threadIdx.x) >> 5;
    int lane = threadIdx.x & 31;
    if (warp >= N_NODES) return;
    int node = warp;

    const uint2* sup2 = (const uint2*)g_suph;   // 4 halfs per uint2
    float4 b = ((const float4*)bias)[lane];
    float4 acc = ((const float4*)y)[(size_t)node * 32 + lane];
    acc.x += b.x; acc.y += b.y; acc.z += b.z; acc.w += b.w;

    int dn = g_deg[node];
    int m  = dn < CAP ? dn : CAP;
    int base = node * CAP;

    #pragma unroll 2
    for (int j = 0; j < m; j++) {
        int2 e = g_bpack[base + j];
        float v = __int_as_float(e.y);
        uint2 p = sup2[(size_t)e.x * 32 + lane];
        float2 f0 = __half22float2(*(__half2*)&p.x);
        float2 f1 = __half22float2(*(__half2*)&p.y);
        acc.x = fmaf(v, f0.x, acc.x);
        acc.y = fmaf(v, f0.y, acc.y);
        acc.z = fmaf(v, f1.x, acc.z);
        acc.w = fmaf(v, f1.y, acc.w);
    }

    if (dn > CAP) {  // statistically never; correctness safety net
        int oc = g_ovfn;
        if (oc > OVF_CAP) oc = OVF_CAP;
        for (int k = 0; k < oc; k++) {
            if (g_ovf_dst[k] == node) {
                int s   = g_ovf_src[k];
                float v = g_ovf_val[k];
                uint2 p = sup2[(size_t)s * 32 + lane];
                float2 f0 = __half22float2(*(__half2*)&p.x);
                float2 f1 = __half22float2(*(__half2*)&p.y);
                acc.x = fmaf(v, f0.x, acc.x);
                acc.y = fmaf(v, f0.y, acc.y);
                acc.z = fmaf(v, f1.x, acc.z);
                acc.w = fmaf(v, f1.y, acc.w);
            }
        }
    }

    acc.x = fmaxf(acc.x, 0.f);
    acc.y = fmaxf(acc.y, 0.f);
    acc.z = fmaxf(acc.z, 0.f);
    acc.w = fmaxf(acc.w, 0.f);
    ((float4*)out)[(size_t)node * 32 + lane] = acc;
}

// ---------------- launch -----------------------------------------------------
extern "C" void kernel_launch(void* const* d_in, const int* in_sizes, int n_in,
                              void* d_out, int out_size) {
    const float* x    = (const float*)d_in[0];
    const float* y    = (const float*)d_in[1];
    const int*   esrc = (const int*)d_in[2];
    const int*   edst = (const int*)d_in[3];
    const float* aval = (const float*)d_in[4];
    const float* w    = (const float*)d_in[5];
    const float* bias = (const float*)d_in[6];
    float* out = (float*)d_out;

    __half* suph;
    cudaGetSymbolAddress((void**)&suph, g_suph);

    cudaFuncSetAttribute(gemm_mma_kernel,
                         cudaFuncAttributeMaxDynamicSharedMemorySize, SM_GEMM);

    zero_kernel<<<(N_NODES + 255) / 256, 256>>>();
    bucket_kernel<<<(N_EDGES + 255) / 256, 256>>>(esrc, edst, aval);
    gemm_mma_kernel<<<GEMM_CTAS, 256, SM_GEMM>>>(x, w, suph);
    gather_kernel<<<(N_NODES * 32 + 255) / 256, 256>>>(y, bias, out);
}